// round 1
// baseline (speedup 1.0000x reference)
#include <cuda_runtime.h>

#define NMAX 100000
#define EMAX 1600000
#define NSLOPE_ATTN 0.2f
#define NSLOPE_ACT 0.01f

// -------- scratch (static device allocations; no cudaMalloc) --------
__device__ float g_h[NMAX * 64];     // per-layer transformed features
__device__ float g_x[NMAX * 64];     // activations between layers
__device__ float g_el[NMAX];
__device__ float g_er[NMAX];
__device__ int   g_deg[NMAX];
__device__ int   g_row[NMAX + 1];
__device__ int   g_cur[NMAX];
__device__ int   g_csr[EMAX];        // src ids grouped by dst
__device__ int   g_bsum[128];

// ---------------- CSR build ----------------
__global__ void k_zero_deg(int n) {
    int i = blockIdx.x * blockDim.x + threadIdx.x;
    if (i < n) g_deg[i] = 0;
}

__global__ void k_hist(const int* __restrict__ dst, int e) {
    int i = blockIdx.x * blockDim.x + threadIdx.x;
    if (i < e) atomicAdd(&g_deg[dst[i]], 1);
}

__global__ void k_scan1(int n) {
    __shared__ int s[1024];
    int tid = threadIdx.x;
    int i = blockIdx.x * 1024 + tid;
    int v = (i < n) ? g_deg[i] : 0;
    s[tid] = v;
    __syncthreads();
    for (int off = 1; off < 1024; off <<= 1) {
        int t = (tid >= off) ? s[tid - off] : 0;
        __syncthreads();
        s[tid] += t;
        __syncthreads();
    }
    if (i < n) g_row[i] = s[tid] - v;       // exclusive
    if (tid == 1023) g_bsum[blockIdx.x] = s[1023];
}

__global__ void k_scan2(int nb) {
    if (threadIdx.x == 0 && blockIdx.x == 0) {
        int run = 0;
        for (int b = 0; b < nb; b++) {
            int t = g_bsum[b];
            g_bsum[b] = run;
            run += t;
        }
    }
}

__global__ void k_scan3(int n, int e) {
    int i = blockIdx.x * blockDim.x + threadIdx.x;
    if (i < n) {
        int r = g_row[i] + g_bsum[i >> 10];
        g_row[i] = r;
        g_cur[i] = r;
    }
    if (i == 0) g_row[n] = e;
}

__global__ void k_fill(const int* __restrict__ src, const int* __restrict__ dst, int e) {
    int i = blockIdx.x * blockDim.x + threadIdx.x;
    if (i < e) {
        int p = atomicAdd(&g_cur[dst[i]], 1);
        g_csr[p] = src[i];
    }
}

// ---------------- transforms ----------------
// Layer 1: Fin=3, Fout=64. One warp per node; lane handles features (lane, lane+32).
__global__ void k_xform_f3(const float* __restrict__ x, const float* __restrict__ W,
                           const float* __restrict__ al, const float* __restrict__ ar, int n) {
    int warp = (blockIdx.x * blockDim.x + threadIdx.x) >> 5;
    int lane = threadIdx.x & 31;
    if (warp >= n) return;
    float x0 = __ldg(&x[warp * 3 + 0]);
    float x1 = __ldg(&x[warp * 3 + 1]);
    float x2 = __ldg(&x[warp * 3 + 2]);
    int f0 = lane, f1 = lane + 32;
    float h0 = x0 * __ldg(&W[f0]) + x1 * __ldg(&W[64 + f0]) + x2 * __ldg(&W[128 + f0]);
    float h1 = x0 * __ldg(&W[f1]) + x1 * __ldg(&W[64 + f1]) + x2 * __ldg(&W[128 + f1]);
    g_h[warp * 64 + f0] = h0;
    g_h[warp * 64 + f1] = h1;
    float el = h0 * __ldg(&al[f0]) + h1 * __ldg(&al[f1]);
    float er = h0 * __ldg(&ar[f0]) + h1 * __ldg(&ar[f1]);
    for (int o = 16; o; o >>= 1) {
        el += __shfl_xor_sync(~0u, el, o);
        er += __shfl_xor_sync(~0u, er, o);
    }
    if (lane == 0) { g_el[warp] = el; g_er[warp] = er; }
}

// Layer 2: Fin=64, Fout=64. W in shared; x broadcast via shuffle.
// Lane handles features (2*lane, 2*lane+1).
__global__ void k_xform_f64(const float* __restrict__ x, const float* __restrict__ W,
                            const float* __restrict__ al, const float* __restrict__ ar, int n) {
    __shared__ float sW[64 * 64];
    int tid = threadIdx.x;
    for (int i = tid; i < 64 * 64; i += blockDim.x) sW[i] = __ldg(&W[i]);
    __syncthreads();
    int warp = (blockIdx.x * blockDim.x + tid) >> 5;
    int lane = tid & 31;
    if (warp >= n) return;
    float2 xr = ((const float2*)x)[warp * 32 + lane];
    float a0 = 0.f, a1 = 0.f;
#pragma unroll
    for (int j = 0; j < 32; j++) {
        float xa = __shfl_sync(~0u, xr.x, j);
        float xb = __shfl_sync(~0u, xr.y, j);
        float2 w0 = ((const float2*)sW)[(2 * j) * 32 + lane];
        float2 w1 = ((const float2*)sW)[(2 * j + 1) * 32 + lane];
        a0 += xa * w0.x + xb * w1.x;
        a1 += xa * w0.y + xb * w1.y;
    }
    ((float2*)g_h)[warp * 32 + lane] = make_float2(a0, a1);
    float el = a0 * __ldg(&al[2 * lane]) + a1 * __ldg(&al[2 * lane + 1]);
    float er = a0 * __ldg(&ar[2 * lane]) + a1 * __ldg(&ar[2 * lane + 1]);
    for (int o = 16; o; o >>= 1) {
        el += __shfl_xor_sync(~0u, el, o);
        er += __shfl_xor_sync(~0u, er, o);
    }
    if (lane == 0) { g_el[warp] = el; g_er[warp] = er; }
}

// Layer 3 transform: Fin=64, Fout=3. Thread per node. h stored into g_h[i*3..].
__global__ void k_xform_out(const float* __restrict__ x, const float* __restrict__ W,
                            const float* __restrict__ al, const float* __restrict__ ar, int n) {
    int i = blockIdx.x * blockDim.x + threadIdx.x;
    if (i >= n) return;
    float h0 = 0.f, h1 = 0.f, h2 = 0.f;
    const float4* xp = (const float4*)&x[i * 64];
#pragma unroll
    for (int j = 0; j < 16; j++) {
        float4 xv = __ldg(&xp[j]);
        int r = 4 * j;
        h0 += xv.x * __ldg(&W[(r + 0) * 3 + 0]) + xv.y * __ldg(&W[(r + 1) * 3 + 0]) +
              xv.z * __ldg(&W[(r + 2) * 3 + 0]) + xv.w * __ldg(&W[(r + 3) * 3 + 0]);
        h1 += xv.x * __ldg(&W[(r + 0) * 3 + 1]) + xv.y * __ldg(&W[(r + 1) * 3 + 1]) +
              xv.z * __ldg(&W[(r + 2) * 3 + 1]) + xv.w * __ldg(&W[(r + 3) * 3 + 1]);
        h2 += xv.x * __ldg(&W[(r + 0) * 3 + 2]) + xv.y * __ldg(&W[(r + 1) * 3 + 2]) +
              xv.z * __ldg(&W[(r + 2) * 3 + 2]) + xv.w * __ldg(&W[(r + 3) * 3 + 2]);
    }
    g_h[i * 3 + 0] = h0;
    g_h[i * 3 + 1] = h1;
    g_h[i * 3 + 2] = h2;
    g_el[i] = h0 * __ldg(&al[0]) + h1 * __ldg(&al[1]) + h2 * __ldg(&al[2]);
    g_er[i] = h0 * __ldg(&ar[0]) + h1 * __ldg(&ar[1]) + h2 * __ldg(&ar[2]);
}

// ---------------- aggregation (edge softmax + weighted sum) ----------------
// Warp per dst node, online softmax; lane handles features (2*lane, 2*lane+1).
__global__ void k_agg64(const float* __restrict__ b, float* __restrict__ out, int n, int act) {
    int warp = (blockIdx.x * blockDim.x + threadIdx.x) >> 5;
    int lane = threadIdx.x & 31;
    if (warp >= n) return;
    int beg = g_row[warp], end = g_row[warp + 1];
    float ern = g_er[warp];
    float m = -1e30f, denom = 0.f, a0 = 0.f, a1 = 0.f;
    for (int k = beg; k < end; k++) {
        int s = g_csr[k];
        float e = g_el[s] + ern;
        e = e > 0.f ? e : NSLOPE_ATTN * e;
        float mn = fmaxf(m, e);
        float sc = __expf(m - mn);
        float w = __expf(e - mn);
        float2 hv = ((const float2*)g_h)[s * 32 + lane];
        denom = denom * sc + w;
        a0 = a0 * sc + w * hv.x;
        a1 = a1 * sc + w * hv.y;
        m = mn;
    }
    float inv = (end > beg) ? 1.f / denom : 0.f;
    float o0 = a0 * inv + __ldg(&b[2 * lane]);
    float o1 = a1 * inv + __ldg(&b[2 * lane + 1]);
    if (act) {
        o0 = o0 > 0.f ? o0 : NSLOPE_ACT * o0;
        o1 = o1 > 0.f ? o1 : NSLOPE_ACT * o1;
    }
    ((float2*)out)[warp * 32 + lane] = make_float2(o0, o1);
}

// Thread per dst node for Fout=3, writes final output (no activation).
__global__ void k_agg3(const float* __restrict__ b, float* __restrict__ out, int n) {
    int i = blockIdx.x * blockDim.x + threadIdx.x;
    if (i >= n) return;
    int beg = g_row[i], end = g_row[i + 1];
    float ern = g_er[i];
    float m = -1e30f, denom = 0.f, a0 = 0.f, a1 = 0.f, a2 = 0.f;
    for (int k = beg; k < end; k++) {
        int s = g_csr[k];
        float e = g_el[s] + ern;
        e = e > 0.f ? e : NSLOPE_ATTN * e;
        float mn = fmaxf(m, e);
        float sc = __expf(m - mn);
        float w = __expf(e - mn);
        denom = denom * sc + w;
        a0 = a0 * sc + w * g_h[s * 3 + 0];
        a1 = a1 * sc + w * g_h[s * 3 + 1];
        a2 = a2 * sc + w * g_h[s * 3 + 2];
        m = mn;
    }
    float inv = (end > beg) ? 1.f / denom : 0.f;
    out[i * 3 + 0] = a0 * inv + __ldg(&b[0]);
    out[i * 3 + 1] = a1 * inv + __ldg(&b[1]);
    out[i * 3 + 2] = a2 * inv + __ldg(&b[2]);
}

// ---------------- launch ----------------
extern "C" void kernel_launch(void* const* d_in, const int* in_sizes, int n_in,
                              void* d_out, int out_size) {
    const float* feat = (const float*)d_in[0];
    const int*   src  = (const int*)d_in[1];
    const int*   dst  = (const int*)d_in[2];
    const float* W1 = (const float*)d_in[3];
    const float* al1 = (const float*)d_in[4];
    const float* ar1 = (const float*)d_in[5];
    const float* b1 = (const float*)d_in[6];
    const float* W2 = (const float*)d_in[7];
    const float* al2 = (const float*)d_in[8];
    const float* ar2 = (const float*)d_in[9];
    const float* b2 = (const float*)d_in[10];
    const float* W3 = (const float*)d_in[11];
    const float* al3 = (const float*)d_in[12];
    const float* ar3 = (const float*)d_in[13];
    const float* b3 = (const float*)d_in[14];

    int n = in_sizes[0] / 3;
    int e = in_sizes[1];
    float* out = (float*)d_out;

    void* gx_v = nullptr;
    cudaGetSymbolAddress(&gx_v, g_x);
    float* gx = (float*)gx_v;

    int tb = 256;
    int nodeBlocks = (n + tb - 1) / tb;          // thread-per-node kernels
    int warpNodeBlocks = (n + (tb / 32) - 1) / (tb / 32);  // warp-per-node kernels
    int edgeBlocks = (e + tb - 1) / tb;
    int scanBlocks = (n + 1023) / 1024;

    // CSR build (dst-grouped)
    k_zero_deg<<<nodeBlocks, tb>>>(n);
    k_hist<<<edgeBlocks, tb>>>(dst, e);
    k_scan1<<<scanBlocks, 1024>>>(n);
    k_scan2<<<1, 32>>>(scanBlocks);
    k_scan3<<<nodeBlocks, tb>>>(n, e);
    k_fill<<<edgeBlocks, tb>>>(src, dst, e);

    // Layer 1: 3 -> 64
    k_xform_f3<<<warpNodeBlocks, tb>>>(feat, W1, al1, ar1, n);
    k_agg64<<<warpNodeBlocks, tb>>>(b1, gx, n, 1);

    // Layer 2: 64 -> 64
    k_xform_f64<<<warpNodeBlocks, tb>>>(gx, W2, al2, ar2, n);
    k_agg64<<<warpNodeBlocks, tb>>>(b2, gx, n, 1);

    // Layer 3: 64 -> 3
    k_xform_out<<<nodeBlocks, tb>>>(gx, W3, al3, ar3, n);
    k_agg3<<<nodeBlocks, tb>>>(b3, out, n);
}

// round 2
// speedup vs baseline: 1.1757x; 1.1757x over previous
#include <cuda_runtime.h>

#define NMAX 100000
#define EMAX 1600000
#define NSLOPE_ATTN 0.2f
#define NSLOPE_ACT 0.01f

// -------- static scratch --------
__device__ float g_h[NMAX * 64];     // layer-1 transformed features
__device__ float g_x[NMAX * 64];     // layer-2 transformed features
__device__ float g_h3[NMAX * 3];     // layer-3 transformed features
__device__ float g_el[NMAX], g_er[NMAX];
__device__ float g_el2[NMAX], g_er2[NMAX];
__device__ int   g_deg[NMAX];
__device__ int   g_row[NMAX + 1];
__device__ int   g_cur[NMAX];
__device__ int   g_csr[EMAX];
__device__ int   g_bsum[128];

// ---------------- CSR build ----------------
__global__ void k_hist(const int* __restrict__ dst, int e) {
    int i = blockIdx.x * blockDim.x + threadIdx.x;
    int i4 = i * 4;
    if (i4 + 3 < e) {
        int4 d = *(const int4*)(dst + i4);
        atomicAdd(&g_deg[d.x], 1);
        atomicAdd(&g_deg[d.y], 1);
        atomicAdd(&g_deg[d.z], 1);
        atomicAdd(&g_deg[d.w], 1);
    } else {
        for (int j = i4; j < e; j++) atomicAdd(&g_deg[dst[j]], 1);
    }
}

__global__ void k_scan1(int n) {
    __shared__ int s[1024];
    int tid = threadIdx.x;
    int i = blockIdx.x * 1024 + tid;
    int v = (i < n) ? g_deg[i] : 0;
    s[tid] = v;
    __syncthreads();
    for (int off = 1; off < 1024; off <<= 1) {
        int t = (tid >= off) ? s[tid - off] : 0;
        __syncthreads();
        s[tid] += t;
        __syncthreads();
    }
    if (i < n) g_row[i] = s[tid] - v;       // exclusive within block
    if (tid == 1023) g_bsum[blockIdx.x] = s[1023];
}

__global__ void k_scan2(int nb) {
    __shared__ int s[128];
    int t = threadIdx.x;
    int v = (t < nb) ? g_bsum[t] : 0;
    s[t] = v;
    __syncthreads();
    for (int off = 1; off < 128; off <<= 1) {
        int u = (t >= off) ? s[t - off] : 0;
        __syncthreads();
        s[t] += u;
        __syncthreads();
    }
    if (t < nb) g_bsum[t] = s[t] - v;       // exclusive block offsets
}

__global__ void k_scan3(int n, int e) {
    int i = blockIdx.x * blockDim.x + threadIdx.x;
    if (i < n) {
        int r = g_row[i] + g_bsum[i >> 10];
        g_row[i] = r;
        g_cur[i] = r;
    }
    if (i == 0) g_row[n] = e;
}

__global__ void k_fill(const int* __restrict__ src, const int* __restrict__ dst, int e) {
    int i = blockIdx.x * blockDim.x + threadIdx.x;
    int i4 = i * 4;
    if (i4 + 3 < e) {
        int4 d = *(const int4*)(dst + i4);
        int4 s = *(const int4*)(src + i4);
        g_csr[atomicAdd(&g_cur[d.x], 1)] = s.x;
        g_csr[atomicAdd(&g_cur[d.y], 1)] = s.y;
        g_csr[atomicAdd(&g_cur[d.z], 1)] = s.z;
        g_csr[atomicAdd(&g_cur[d.w], 1)] = s.w;
    } else {
        for (int j = i4; j < e; j++)
            g_csr[atomicAdd(&g_cur[dst[j]], 1)] = src[j];
    }
}

// ---------------- layer-1 transform (Fin=3 -> 64) ----------------
__global__ void k_xform_f3(const float* __restrict__ x, const float* __restrict__ W,
                           const float* __restrict__ al, const float* __restrict__ ar, int n) {
    int warp = (blockIdx.x * blockDim.x + threadIdx.x) >> 5;
    int lane = threadIdx.x & 31;
    if (warp >= n) return;
    float x0 = __ldg(&x[warp * 3 + 0]);
    float x1 = __ldg(&x[warp * 3 + 1]);
    float x2 = __ldg(&x[warp * 3 + 2]);
    int f0 = lane, f1 = lane + 32;
    float h0 = x0 * __ldg(&W[f0]) + x1 * __ldg(&W[64 + f0]) + x2 * __ldg(&W[128 + f0]);
    float h1 = x0 * __ldg(&W[f1]) + x1 * __ldg(&W[64 + f1]) + x2 * __ldg(&W[128 + f1]);
    g_h[warp * 64 + f0] = h0;
    g_h[warp * 64 + f1] = h1;
    float el = h0 * __ldg(&al[f0]) + h1 * __ldg(&al[f1]);
    float er = h0 * __ldg(&ar[f0]) + h1 * __ldg(&ar[f1]);
    for (int o = 16; o; o >>= 1) {
        el += __shfl_xor_sync(~0u, el, o);
        er += __shfl_xor_sync(~0u, er, o);
    }
    if (lane == 0) { g_el[warp] = el; g_er[warp] = er; }
}

// ---------------- aggregation core (64-wide, warp per node, unroll-4) ----------------
// Gathers H (float2 per lane) + EL, online softmax, returns (a0,a1)/denom in o0,o1.
__device__ __forceinline__ void agg64_node(int node, int lane,
                                           const float2* __restrict__ H,
                                           const float* __restrict__ EL,
                                           const float* __restrict__ ER,
                                           float& o0, float& o1) {
    int beg = g_row[node], end = g_row[node + 1];
    float ern = ER[node];
    float m = -1e30f, denom = 0.f, a0 = 0.f, a1 = 0.f;
    int k = beg;
    for (; k + 4 <= end; k += 4) {
        int s0 = g_csr[k + 0];
        int s1 = g_csr[k + 1];
        int s2 = g_csr[k + 2];
        int s3 = g_csr[k + 3];
        float e0 = EL[s0] + ern;
        float e1 = EL[s1] + ern;
        float e2 = EL[s2] + ern;
        float e3 = EL[s3] + ern;
        float2 h0 = H[s0 * 32 + lane];
        float2 h1 = H[s1 * 32 + lane];
        float2 h2 = H[s2 * 32 + lane];
        float2 h3 = H[s3 * 32 + lane];
        e0 = e0 > 0.f ? e0 : NSLOPE_ATTN * e0;
        e1 = e1 > 0.f ? e1 : NSLOPE_ATTN * e1;
        e2 = e2 > 0.f ? e2 : NSLOPE_ATTN * e2;
        e3 = e3 > 0.f ? e3 : NSLOPE_ATTN * e3;
        float mx = fmaxf(fmaxf(e0, e1), fmaxf(e2, e3));
        float mn = fmaxf(m, mx);
        float sc = __expf(m - mn);
        float w0 = __expf(e0 - mn);
        float w1 = __expf(e1 - mn);
        float w2 = __expf(e2 - mn);
        float w3 = __expf(e3 - mn);
        denom = denom * sc + ((w0 + w1) + (w2 + w3));
        a0 = a0 * sc + w0 * h0.x + w1 * h1.x + w2 * h2.x + w3 * h3.x;
        a1 = a1 * sc + w0 * h0.y + w1 * h1.y + w2 * h2.y + w3 * h3.y;
        m = mn;
    }
    for (; k < end; k++) {
        int s = g_csr[k];
        float e = EL[s] + ern;
        e = e > 0.f ? e : NSLOPE_ATTN * e;
        float2 hv = H[s * 32 + lane];
        float mn = fmaxf(m, e);
        float sc = __expf(m - mn);
        float w = __expf(e - mn);
        denom = denom * sc + w;
        a0 = a0 * sc + w * hv.x;
        a1 = a1 * sc + w * hv.y;
        m = mn;
    }
    float inv = (end > beg) ? 1.f / denom : 0.f;
    o0 = a0 * inv;
    o1 = a1 * inv;
}

// Layer-1 agg + fused W2 transform epilogue. Grid-stride over nodes; W2 in shared.
__global__ __launch_bounds__(256) void k_agg_l1(
        const float* __restrict__ b1, const float* __restrict__ W2,
        const float* __restrict__ al2, const float* __restrict__ ar2, int n) {
    __shared__ float sW[64 * 64];
    int tid = threadIdx.x;
    for (int i = tid; i < 64 * 64; i += blockDim.x) sW[i] = __ldg(&W2[i]);
    __syncthreads();
    int lane = tid & 31;
    int warpInBlock = tid >> 5;
    int warpsPerBlock = blockDim.x >> 5;
    int totalWarps = gridDim.x * warpsPerBlock;
    // hoisted per-lane constants
    float bb0 = __ldg(&b1[2 * lane]), bb1 = __ldg(&b1[2 * lane + 1]);
    float a2l0 = __ldg(&al2[2 * lane]), a2l1 = __ldg(&al2[2 * lane + 1]);
    float a2r0 = __ldg(&ar2[2 * lane]), a2r1 = __ldg(&ar2[2 * lane + 1]);
    const float2* H = (const float2*)g_h;
    for (int node = blockIdx.x * warpsPerBlock + warpInBlock; node < n; node += totalWarps) {
        float o0, o1;
        agg64_node(node, lane, H, g_el, g_er, o0, o1);
        o0 += bb0; o1 += bb1;
        o0 = o0 > 0.f ? o0 : NSLOPE_ACT * o0;          // inter-layer leaky relu
        o1 = o1 > 0.f ? o1 : NSLOPE_ACT * o1;
        // h2 = x @ W2 via shuffle-broadcast
        float h0 = 0.f, h1 = 0.f;
#pragma unroll
        for (int j = 0; j < 32; j++) {
            float xa = __shfl_sync(~0u, o0, j);
            float xb = __shfl_sync(~0u, o1, j);
            float2 w0 = ((const float2*)sW)[(2 * j) * 32 + lane];
            float2 w1 = ((const float2*)sW)[(2 * j + 1) * 32 + lane];
            h0 += xa * w0.x + xb * w1.x;
            h1 += xa * w0.y + xb * w1.y;
        }
        ((float2*)g_x)[node * 32 + lane] = make_float2(h0, h1);
        float el = h0 * a2l0 + h1 * a2l1;
        float er = h0 * a2r0 + h1 * a2r1;
        for (int o = 16; o; o >>= 1) {
            el += __shfl_xor_sync(~0u, el, o);
            er += __shfl_xor_sync(~0u, er, o);
        }
        if (lane == 0) { g_el2[node] = el; g_er2[node] = er; }
    }
}

// Layer-2 agg + fused W3 transform epilogue (64 -> 3). Warp per node.
__global__ __launch_bounds__(256) void k_agg_l2(
        const float* __restrict__ b2, const float* __restrict__ W3,
        const float* __restrict__ al3, const float* __restrict__ ar3, int n) {
    int tid = blockIdx.x * blockDim.x + threadIdx.x;
    int node = tid >> 5;
    int lane = tid & 31;
    if (node >= n) return;
    float bb0 = __ldg(&b2[2 * lane]), bb1 = __ldg(&b2[2 * lane + 1]);
    // W3 rows for this lane's two features
    float w00 = __ldg(&W3[(2 * lane) * 3 + 0]);
    float w01 = __ldg(&W3[(2 * lane) * 3 + 1]);
    float w02 = __ldg(&W3[(2 * lane) * 3 + 2]);
    float w10 = __ldg(&W3[(2 * lane + 1) * 3 + 0]);
    float w11 = __ldg(&W3[(2 * lane + 1) * 3 + 1]);
    float w12 = __ldg(&W3[(2 * lane + 1) * 3 + 2]);
    const float2* H = (const float2*)g_x;
    float o0, o1;
    agg64_node(node, lane, H, g_el2, g_er2, o0, o1);
    o0 += bb0; o1 += bb1;
    o0 = o0 > 0.f ? o0 : NSLOPE_ACT * o0;
    o1 = o1 > 0.f ? o1 : NSLOPE_ACT * o1;
    float p0 = o0 * w00 + o1 * w10;
    float p1 = o0 * w01 + o1 * w11;
    float p2 = o0 * w02 + o1 * w12;
    for (int o = 16; o; o >>= 1) {
        p0 += __shfl_xor_sync(~0u, p0, o);
        p1 += __shfl_xor_sync(~0u, p1, o);
        p2 += __shfl_xor_sync(~0u, p2, o);
    }
    if (lane == 0) {
        g_h3[node * 3 + 0] = p0;
        g_h3[node * 3 + 1] = p1;
        g_h3[node * 3 + 2] = p2;
        g_el[node] = p0 * __ldg(&al3[0]) + p1 * __ldg(&al3[1]) + p2 * __ldg(&al3[2]);
        g_er[node] = p0 * __ldg(&ar3[0]) + p1 * __ldg(&ar3[1]) + p2 * __ldg(&ar3[2]);
    }
}

// Final layer agg (3-wide): warp per node, lanes parallel over edges.
__global__ __launch_bounds__(256) void k_agg3(const float* __restrict__ b, float* __restrict__ out, int n) {
    int tid = blockIdx.x * blockDim.x + threadIdx.x;
    int node = tid >> 5;
    int lane = tid & 31;
    if (node >= n) return;
    int beg = g_row[node], end = g_row[node + 1];
    float ern = g_er[node];
    float m = -1e30f, den = 0.f, a0 = 0.f, a1 = 0.f, a2 = 0.f;
    for (int k = beg + lane; k < end; k += 32) {
        int s = g_csr[k];
        float e = g_el[s] + ern;
        e = e > 0.f ? e : NSLOPE_ATTN * e;
        float h0 = g_h3[s * 3 + 0];
        float h1 = g_h3[s * 3 + 1];
        float h2 = g_h3[s * 3 + 2];
        float mn = fmaxf(m, e);
        float sc = __expf(m - mn);
        float w = __expf(e - mn);
        den = den * sc + w;
        a0 = a0 * sc + w * h0;
        a1 = a1 * sc + w * h1;
        a2 = a2 * sc + w * h2;
        m = mn;
    }
    // combine lanes (online-softmax merge)
    for (int o = 16; o; o >>= 1) {
        float mo = __shfl_xor_sync(~0u, m, o);
        float dn = __shfl_xor_sync(~0u, den, o);
        float b0 = __shfl_xor_sync(~0u, a0, o);
        float b1v = __shfl_xor_sync(~0u, a1, o);
        float b2v = __shfl_xor_sync(~0u, a2, o);
        float mn = fmaxf(m, mo);
        float s1 = __expf(m - mn);
        float s2 = __expf(mo - mn);
        den = den * s1 + dn * s2;
        a0 = a0 * s1 + b0 * s2;
        a1 = a1 * s1 + b1v * s2;
        a2 = a2 * s1 + b2v * s2;
        m = mn;
    }
    if (lane == 0) {
        float inv = (end > beg) ? 1.f / den : 0.f;
        out[node * 3 + 0] = a0 * inv + __ldg(&b[0]);
        out[node * 3 + 1] = a1 * inv + __ldg(&b[1]);
        out[node * 3 + 2] = a2 * inv + __ldg(&b[2]);
    }
}

// ---------------- launch ----------------
extern "C" void kernel_launch(void* const* d_in, const int* in_sizes, int n_in,
                              void* d_out, int out_size) {
    const float* feat = (const float*)d_in[0];
    const int*   src  = (const int*)d_in[1];
    const int*   dst  = (const int*)d_in[2];
    const float* W1 = (const float*)d_in[3];
    const float* al1 = (const float*)d_in[4];
    const float* ar1 = (const float*)d_in[5];
    const float* b1 = (const float*)d_in[6];
    const float* W2 = (const float*)d_in[7];
    const float* al2 = (const float*)d_in[8];
    const float* ar2 = (const float*)d_in[9];
    const float* b2 = (const float*)d_in[10];
    const float* W3 = (const float*)d_in[11];
    const float* al3 = (const float*)d_in[12];
    const float* ar3 = (const float*)d_in[13];
    const float* b3 = (const float*)d_in[14];

    int n = in_sizes[0] / 3;
    int e = in_sizes[1];
    float* out = (float*)d_out;

    void* deg_v = nullptr;
    cudaGetSymbolAddress(&deg_v, g_deg);

    int tb = 256;
    int nodeBlocks = (n + tb - 1) / tb;
    int warpNodeBlocks = (n + (tb / 32) - 1) / (tb / 32);
    int e4 = (e + 3) / 4;
    int edge4Blocks = (e4 + tb - 1) / tb;
    int scanBlocks = (n + 1023) / 1024;

    // CSR build (dst-grouped)
    cudaMemsetAsync(deg_v, 0, n * sizeof(int), 0);
    k_hist<<<edge4Blocks, tb>>>(dst, e);
    k_scan1<<<scanBlocks, 1024>>>(n);
    k_scan2<<<1, 128>>>(scanBlocks);
    k_scan3<<<nodeBlocks, tb>>>(n, e);
    k_fill<<<edge4Blocks, tb>>>(src, dst, e);

    // Layer 1 transform
    k_xform_f3<<<warpNodeBlocks, tb>>>(feat, W1, al1, ar1, n);
    // Layer 1 agg + fused layer-2 transform
    int aggBlocks = 1184;
    if (aggBlocks > warpNodeBlocks) aggBlocks = warpNodeBlocks;
    k_agg_l1<<<aggBlocks, tb>>>(b1, W2, al2, ar2, n);
    // Layer 2 agg + fused layer-3 transform
    k_agg_l2<<<warpNodeBlocks, tb>>>(b2, W3, al3, ar3, n);
    // Final agg
    k_agg3<<<warpNodeBlocks, tb>>>(b3, out, n);
}